// round 3
// baseline (speedup 1.0000x reference)
#include <cuda_runtime.h>
#include <math.h>

#define SQ   2048
#define BB   2
#define DD   1024
#define HH   16
#define CC   64
#define HC   1024
#define NROW (SQ*BB)   /* 4096 */

// Scratch (allocation-free): Q/K/V in [b][h][s][c], attn output in [s][b][h*C]
__device__ float g_q[BB*HH*SQ*CC];
__device__ float g_k[BB*HH*SQ*CC];
__device__ float g_v[BB*HH*SQ*CC];
__device__ float g_ao[(size_t)NROW*HC];

// ---------------------------------------------------------------------------
// Kernel 1: QKV projection GEMM (64x64 tile, 4x4 micro-tile) with fused
// RMSNorm (over C=64, exactly one tile column-group) + RoPE epilogue.
// grid = (H, NROW/64, 3)   z: 0=Q, 1=K, 2=V
// ---------------------------------------------------------------------------
__global__ __launch_bounds__(256) void qkv_kernel(
    const float* __restrict__ x, const float* __restrict__ rope,
    const float* __restrict__ Wq, const float* __restrict__ Wk,
    const float* __restrict__ Wv, const float* __restrict__ qw,
    const float* __restrict__ kw)
{
    const int h  = blockIdx.x;
    const int r0 = blockIdx.y * 64;
    const int z  = blockIdx.z;
    const float* __restrict__ W = (z == 0) ? Wq : (z == 1) ? Wk : Wv;
    const int n0 = h * CC;

    __shared__ float As[32][65];   // [k][m], pad 65 -> conflict-free transpose stores
    __shared__ float Bs[32][64];   // [k][n]
    __shared__ float outs[64][68]; // result tile, pad 68 keeps float4 alignment
    __shared__ float rstd_s[64];

    const int tid = threadIdx.x;
    const int tx = tid & 15, ty = tid >> 4;

    float acc[4][4];
#pragma unroll
    for (int i = 0; i < 4; i++)
#pragma unroll
        for (int j = 0; j < 4; j++) acc[i][j] = 0.f;

    for (int k0 = 0; k0 < DD; k0 += 32) {
#pragma unroll
        for (int q = 0; q < 2; q++) {
            int lin = tid + q * 256;         // 0..511 float4 slots
            int mm  = lin >> 3;              // 0..63
            int kk  = (lin & 7) << 2;        // 0..28
            float4 a4 = *(const float4*)&x[(size_t)(r0 + mm) * DD + k0 + kk];
            As[kk + 0][mm] = a4.x; As[kk + 1][mm] = a4.y;
            As[kk + 2][mm] = a4.z; As[kk + 3][mm] = a4.w;
            int kb = lin >> 4;               // 0..31
            int n4 = (lin & 15) << 2;        // 0..60
            *(float4*)&Bs[kb][n4] = *(const float4*)&W[(size_t)(k0 + kb) * HC + n0 + n4];
        }
        __syncthreads();
#pragma unroll
        for (int kk = 0; kk < 32; kk++) {
            float a[4];
#pragma unroll
            for (int i = 0; i < 4; i++) a[i] = As[kk][ty * 4 + i];
            float4 b4 = *(const float4*)&Bs[kk][tx * 4];
#pragma unroll
            for (int i = 0; i < 4; i++) {
                acc[i][0] = fmaf(a[i], b4.x, acc[i][0]);
                acc[i][1] = fmaf(a[i], b4.y, acc[i][1]);
                acc[i][2] = fmaf(a[i], b4.z, acc[i][2]);
                acc[i][3] = fmaf(a[i], b4.w, acc[i][3]);
            }
        }
        __syncthreads();
    }

#pragma unroll
    for (int i = 0; i < 4; i++)
        *(float4*)&outs[ty * 4 + i][tx * 4] =
            make_float4(acc[i][0], acc[i][1], acc[i][2], acc[i][3]);
    __syncthreads();

    if (z < 2 && tid < 64) {
        float ss = 0.f;
#pragma unroll
        for (int c = 0; c < 64; c++) { float v = outs[tid][c]; ss = fmaf(v, v, ss); }
        rstd_s[tid] = rsqrtf(ss * (1.0f / 64.0f) + 1e-6f);
    }
    __syncthreads();

    float* __restrict__ dst = (z == 0) ? g_q : (z == 1) ? g_k : g_v;
    const float* __restrict__ nw = (z == 0) ? qw : kw;
#pragma unroll
    for (int it = 0; it < 16; it++) {
        int idx = tid + it * 256;
        int row = idx >> 6, c = idx & 63;
        int r = r0 + row;
        int s = r >> 1;       // r = s*B + b, B=2
        int b = r & 1;
        float val;
        if (z == 2) {
            val = outs[row][c];
        } else {
            float rs = rstd_s[row];
            int j = c & 31;
            // rope_emb[s][j][0][0] = cos, [s][j][1][0] = sin
            float cosv = rope[(((size_t)s * 32 + j) * 2 + 0) * 2 + 0];
            float sinv = rope[(((size_t)s * 32 + j) * 2 + 1) * 2 + 0];
            if (c < 32) {
                float v0 = outs[row][c]      * rs * nw[c];
                float v1 = outs[row][c + 32] * rs * nw[c + 32];
                val = cosv * v0 - sinv * v1;
            } else {
                float v0 = outs[row][c - 32] * rs * nw[c - 32];
                float v1 = outs[row][c]      * rs * nw[c];
                val = sinv * v0 + cosv * v1;
            }
        }
        dst[((size_t)(b * HH + h) * SQ + s) * CC + c] = val;
    }
}

// ---------------------------------------------------------------------------
// Kernel 2: flash attention, 1 thread = 1 query row. Q/O in registers,
// K/V staged through smem (all lanes read the same key -> broadcast LDS).
// Online softmax with 8-key sub-tiles (one rescale per 8 keys).
// grid = (B*H, S/128), block = 128
// ---------------------------------------------------------------------------
__global__ __launch_bounds__(128) void attn_kernel()
{
    const int bh = blockIdx.x;
    const int qt = blockIdx.y;
    const float* __restrict__ Qp = g_q + (size_t)bh * SQ * CC;
    const float* __restrict__ Kp = g_k + (size_t)bh * SQ * CC;
    const float* __restrict__ Vp = g_v + (size_t)bh * SQ * CC;
    const int tid = threadIdx.x;
    const int qi  = qt * 128 + tid;

    __shared__ float Ks[64][64];
    __shared__ float Vs[64][64];

    const float scale = 0.125f;   // 1/sqrt(64)
    float4 q4[16];
#pragma unroll
    for (int i = 0; i < 16; i++) {
        float4 t = *(const float4*)&Qp[(size_t)qi * CC + i * 4];
        t.x *= scale; t.y *= scale; t.z *= scale; t.w *= scale;
        q4[i] = t;
    }
    float4 o4[16];
#pragma unroll
    for (int i = 0; i < 16; i++) o4[i] = make_float4(0.f, 0.f, 0.f, 0.f);
    float m = -1e30f, l = 0.f;

#pragma unroll 1
    for (int j0 = 0; j0 < SQ; j0 += 64) {
        __syncthreads();
#pragma unroll
        for (int t = 0; t < 8; t++) {
            int lin = tid + t * 128;
            int row = lin >> 4;
            int c4  = (lin & 15) << 2;
            *(float4*)&Ks[row][c4] = *(const float4*)&Kp[(size_t)(j0 + row) * CC + c4];
            *(float4*)&Vs[row][c4] = *(const float4*)&Vp[(size_t)(j0 + row) * CC + c4];
        }
        __syncthreads();
#pragma unroll 1
        for (int sub = 0; sub < 8; sub++) {
            float sc[8];
#pragma unroll
            for (int jj = 0; jj < 8; jj++) {
                int j = sub * 8 + jj;
                float d0 = 0.f, d1 = 0.f, d2 = 0.f, d3 = 0.f;
#pragma unroll
                for (int c = 0; c < 16; c++) {
                    float4 kv = *(const float4*)&Ks[j][c * 4];
                    d0 = fmaf(q4[c].x, kv.x, d0);
                    d1 = fmaf(q4[c].y, kv.y, d1);
                    d2 = fmaf(q4[c].z, kv.z, d2);
                    d3 = fmaf(q4[c].w, kv.w, d3);
                }
                sc[jj] = (d0 + d1) + (d2 + d3);
            }
            float mt = sc[0];
#pragma unroll
            for (int jj = 1; jj < 8; jj++) mt = fmaxf(mt, sc[jj]);
            float mnew = fmaxf(m, mt);
            float corr = __expf(m - mnew);
            l *= corr;
#pragma unroll
            for (int i = 0; i < 16; i++) {
                o4[i].x *= corr; o4[i].y *= corr; o4[i].z *= corr; o4[i].w *= corr;
            }
#pragma unroll
            for (int jj = 0; jj < 8; jj++) {
                float p = __expf(sc[jj] - mnew);
                l += p;
                int j = sub * 8 + jj;
#pragma unroll
                for (int c = 0; c < 16; c++) {
                    float4 vv = *(const float4*)&Vs[j][c * 4];
                    o4[c].x = fmaf(p, vv.x, o4[c].x);
                    o4[c].y = fmaf(p, vv.y, o4[c].y);
                    o4[c].z = fmaf(p, vv.z, o4[c].z);
                    o4[c].w = fmaf(p, vv.w, o4[c].w);
                }
            }
            m = mnew;
        }
    }

    float inv = 1.0f / l;
    int b = bh / HH, h = bh % HH;
    float* __restrict__ op = g_ao + ((size_t)qi * BB + b) * HC + h * CC;
#pragma unroll
    for (int i = 0; i < 16; i++) {
        float4 w = o4[i];
        w.x *= inv; w.y *= inv; w.z *= inv; w.w *= inv;
        *(float4*)&op[i * 4] = w;
    }
}

// ---------------------------------------------------------------------------
// Kernel 3: output projection GEMM  g_ao(4096x1024) @ Wout(1024x1024) -> out
// grid = (D/64, NROW/64)
// ---------------------------------------------------------------------------
__global__ __launch_bounds__(256) void outproj_kernel(
    const float* __restrict__ Wout, float* __restrict__ out)
{
    const int n0 = blockIdx.x * 64;
    const int r0 = blockIdx.y * 64;

    __shared__ float As[32][65];
    __shared__ float Bs[32][64];

    const int tid = threadIdx.x;
    const int tx = tid & 15, ty = tid >> 4;

    float acc[4][4];
#pragma unroll
    for (int i = 0; i < 4; i++)
#pragma unroll
        for (int j = 0; j < 4; j++) acc[i][j] = 0.f;

    for (int k0 = 0; k0 < HC; k0 += 32) {
#pragma unroll
        for (int q = 0; q < 2; q++) {
            int lin = tid + q * 256;
            int mm  = lin >> 3;
            int kk  = (lin & 7) << 2;
            float4 a4 = *(const float4*)&g_ao[(size_t)(r0 + mm) * HC + k0 + kk];
            As[kk + 0][mm] = a4.x; As[kk + 1][mm] = a4.y;
            As[kk + 2][mm] = a4.z; As[kk + 3][mm] = a4.w;
            int kb = lin >> 4;
            int n4 = (lin & 15) << 2;
            *(float4*)&Bs[kb][n4] = *(const float4*)&Wout[(size_t)(k0 + kb) * DD + n0 + n4];
        }
        __syncthreads();
#pragma unroll
        for (int kk = 0; kk < 32; kk++) {
            float a[4];
#pragma unroll
            for (int i = 0; i < 4; i++) a[i] = As[kk][ty * 4 + i];
            float4 b4 = *(const float4*)&Bs[kk][tx * 4];
#pragma unroll
            for (int i = 0; i < 4; i++) {
                acc[i][0] = fmaf(a[i], b4.x, acc[i][0]);
                acc[i][1] = fmaf(a[i], b4.y, acc[i][1]);
                acc[i][2] = fmaf(a[i], b4.z, acc[i][2]);
                acc[i][3] = fmaf(a[i], b4.w, acc[i][3]);
            }
        }
        __syncthreads();
    }

#pragma unroll
    for (int i = 0; i < 4; i++)
        *(float4*)&out[(size_t)(r0 + ty * 4 + i) * DD + n0 + tx * 4] =
            make_float4(acc[i][0], acc[i][1], acc[i][2], acc[i][3]);
}

// ---------------------------------------------------------------------------
extern "C" void kernel_launch(void* const* d_in, const int* in_sizes, int n_in,
                              void* d_out, int out_size)
{
    (void)in_sizes; (void)n_in; (void)out_size;
    const float* x    = (const float*)d_in[0];
    const float* rope = (const float*)d_in[1];
    const float* Wq   = (const float*)d_in[2];
    const float* Wk   = (const float*)d_in[3];
    const float* Wv   = (const float*)d_in[4];
    const float* qw   = (const float*)d_in[5];
    const float* kw   = (const float*)d_in[6];
    const float* Wout = (const float*)d_in[7];
    float* out = (float*)d_out;

    dim3 g1(HH, NROW / 64, 3);
    qkv_kernel<<<g1, 256>>>(x, rope, Wq, Wk, Wv, qw, kw);

    dim3 g2(BB * HH, SQ / 128);
    attn_kernel<<<g2, 128>>>();

    dim3 g3(DD / 64, NROW / 64);
    outproj_kernel<<<g3, 256>>>(Wout, out);
}

// round 7
// speedup vs baseline: 1.0884x; 1.0884x over previous
#include <cuda_runtime.h>
#include <math.h>

#define SQ   2048
#define BB   2
#define DD   1024
#define HH   16
#define CC   64
#define HC   1024
#define NROW (SQ*BB)   /* 4096 */

typedef unsigned long long ull;

// ---- packed f32x2 helpers (sm_100+ PTX) ------------------------------------
__device__ __forceinline__ void ffma2(ull &d, ull a, ull b) {
    asm("fma.rn.f32x2 %0, %1, %2, %0;" : "+l"(d) : "l"(a), "l"(b));
}
__device__ __forceinline__ ull fadd2(ull a, ull b) {
    ull r; asm("add.rn.f32x2 %0, %1, %2;" : "=l"(r) : "l"(a), "l"(b)); return r;
}
__device__ __forceinline__ ull pack2(float a, float b) {
    ull r; asm("mov.b64 %0, {%1, %2};" : "=l"(r) : "f"(a), "f"(b)); return r;
}
__device__ __forceinline__ float2 unpack2(ull v) {
    float2 r; asm("mov.b64 {%0, %1}, %2;" : "=f"(r.x), "=f"(r.y) : "l"(v)); return r;
}
__device__ __forceinline__ float ex2f(float x) {
    float y; asm("ex2.approx.f32 %0, %1;" : "=f"(y) : "f"(x)); return y;
}

// Scratch (allocation-free)
__device__ float g_q[BB*HH*SQ*CC];
__device__ float g_k[BB*HH*SQ*CC];
__device__ float g_v[BB*HH*SQ*CC];
__device__ float g_ao[(size_t)NROW*HC];

// ---------------------------------------------------------------------------
// GEMM tile: 128 rows x 64 cols, 256 threads, 8x4 microtile via FFMA2.
// A staged duplicated: As2[kk][2m]=As2[kk][2m+1]=A[m][kk]  -> (a,a) pairs
// ---------------------------------------------------------------------------
struct MainSmem { float As2[32][260]; float Bs[32][68]; };
struct EpiSmem  { float outs[128][64]; float part[128][16]; float rstd[128]; };

// ---------------------------------------------------------------------------
// Kernel 1: QKV projection + RMSNorm + RoPE.  grid=(HH, NROW/128, 3)
// ---------------------------------------------------------------------------
__global__ __launch_bounds__(256) void qkv_kernel(
    const float* __restrict__ x, const float* __restrict__ rope,
    const float* __restrict__ Wq, const float* __restrict__ Wk,
    const float* __restrict__ Wv, const float* __restrict__ qw,
    const float* __restrict__ kw)
{
    __shared__ union { MainSmem m; EpiSmem e; } sm;

    const int h  = blockIdx.x;
    const int r0 = blockIdx.y * 128;
    const int z  = blockIdx.z;
    const float* __restrict__ W = (z == 0) ? Wq : (z == 1) ? Wk : Wv;
    const int n0 = h * CC;

    const int tid = threadIdx.x;
    const int tx = tid & 15, ty = tid >> 4;

    ull acc[8][2];
#pragma unroll
    for (int i = 0; i < 8; i++) { acc[i][0] = 0ull; acc[i][1] = 0ull; }

    for (int k0 = 0; k0 < DD; k0 += 32) {
#pragma unroll
        for (int q = 0; q < 4; q++) {             // A tile: 128x32, duplicated
            int lin = tid + q * 256;              // 0..1023 float4 slots
            int mm  = lin >> 3;                   // 0..127
            int kk  = (lin & 7) << 2;             // 0..28
            float4 a4 = *(const float4*)&x[(size_t)(r0 + mm) * DD + k0 + kk];
            *(float2*)&sm.m.As2[kk + 0][2 * mm] = make_float2(a4.x, a4.x);
            *(float2*)&sm.m.As2[kk + 1][2 * mm] = make_float2(a4.y, a4.y);
            *(float2*)&sm.m.As2[kk + 2][2 * mm] = make_float2(a4.z, a4.z);
            *(float2*)&sm.m.As2[kk + 3][2 * mm] = make_float2(a4.w, a4.w);
        }
#pragma unroll
        for (int q = 0; q < 2; q++) {             // B tile: 32x64
            int lin = tid + q * 256;
            int kb = lin >> 4;                    // 0..31
            int n4 = (lin & 15) << 2;             // 0..60
            *(float4*)&sm.m.Bs[kb][n4] = *(const float4*)&W[(size_t)(k0 + kb) * HC + n0 + n4];
        }
        __syncthreads();
#pragma unroll
        for (int kk = 0; kk < 32; kk++) {
            const ulonglong2* Ar = (const ulonglong2*)&sm.m.As2[kk][16 * ty];
            ulonglong2 a01 = Ar[0], a23 = Ar[1], a45 = Ar[2], a67 = Ar[3];
            ulonglong2 b2 = *(const ulonglong2*)&sm.m.Bs[kk][tx * 4];
            ffma2(acc[0][0], a01.x, b2.x); ffma2(acc[0][1], a01.x, b2.y);
            ffma2(acc[1][0], a01.y, b2.x); ffma2(acc[1][1], a01.y, b2.y);
            ffma2(acc[2][0], a23.x, b2.x); ffma2(acc[2][1], a23.x, b2.y);
            ffma2(acc[3][0], a23.y, b2.x); ffma2(acc[3][1], a23.y, b2.y);
            ffma2(acc[4][0], a45.x, b2.x); ffma2(acc[4][1], a45.x, b2.y);
            ffma2(acc[5][0], a45.y, b2.x); ffma2(acc[5][1], a45.y, b2.y);
            ffma2(acc[6][0], a67.x, b2.x); ffma2(acc[6][1], a67.x, b2.y);
            ffma2(acc[7][0], a67.y, b2.x); ffma2(acc[7][1], a67.y, b2.y);
        }
        __syncthreads();
    }

    // ---- epilogue: RMSNorm (per row over 64 cols) + RoPE + scatter --------
    if (z < 2) {
#pragma unroll
        for (int i = 0; i < 8; i++) {
            float2 v0 = unpack2(acc[i][0]);
            float2 v1 = unpack2(acc[i][1]);
            float ss = v0.x * v0.x + v0.y * v0.y + v1.x * v1.x + v1.y * v1.y;
            sm.e.part[ty * 8 + i][tx] = ss;
        }
        __syncthreads();
        if (tid < 128) {
            float ss = 0.f;
#pragma unroll
            for (int t = 0; t < 16; t++) ss += sm.e.part[tid][t];
            sm.e.rstd[tid] = rsqrtf(ss * (1.0f / 64.0f) + 1e-6f);
        }
        __syncthreads();
        const float* __restrict__ nw = (z == 0) ? qw : kw;
        float w0 = nw[tx * 4 + 0], w1 = nw[tx * 4 + 1];
        float w2 = nw[tx * 4 + 2], w3 = nw[tx * 4 + 3];
#pragma unroll
        for (int i = 0; i < 8; i++) {
            int row = ty * 8 + i;
            float rs = sm.e.rstd[row];
            float2 v0 = unpack2(acc[i][0]);
            float2 v1 = unpack2(acc[i][1]);
            sm.e.outs[row][tx * 4 + 0] = v0.x * rs * w0;
            sm.e.outs[row][tx * 4 + 1] = v0.y * rs * w1;
            sm.e.outs[row][tx * 4 + 2] = v1.x * rs * w2;
            sm.e.outs[row][tx * 4 + 3] = v1.y * rs * w3;
        }
    } else {
#pragma unroll
        for (int i = 0; i < 8; i++) {
            int row = ty * 8 + i;
            float2 v0 = unpack2(acc[i][0]);
            float2 v1 = unpack2(acc[i][1]);
            sm.e.outs[row][tx * 4 + 0] = v0.x;
            sm.e.outs[row][tx * 4 + 1] = v0.y;
            sm.e.outs[row][tx * 4 + 2] = v1.x;
            sm.e.outs[row][tx * 4 + 3] = v1.y;
        }
    }
    __syncthreads();

    float* __restrict__ dst = (z == 0) ? g_q : (z == 1) ? g_k : g_v;
#pragma unroll
    for (int it = 0; it < 32; it++) {
        int idx = tid + it * 256;
        int row = idx >> 6, c = idx & 63;
        int r = r0 + row;
        int s = r >> 1;       // r = s*B + b, B=2
        int b = r & 1;
        float val;
        if (z == 2) {
            val = sm.e.outs[row][c];
        } else {
            int j = c & 31;
            // rope_emb[s][j][0][0] = cos, [s][j][1][0] = sin
            float cosv = rope[((size_t)s * 32 + j) * 4 + 0];
            float sinv = rope[((size_t)s * 32 + j) * 4 + 2];
            float v0 = sm.e.outs[row][j];
            float v1 = sm.e.outs[row][j + 32];
            val = (c < 32) ? (cosv * v0 - sinv * v1) : (sinv * v0 + cosv * v1);
        }
        dst[((size_t)(b * HH + h) * SQ + s) * CC + c] = val;
    }
}

// ---------------------------------------------------------------------------
// Kernel 2: attention, constant-max softmax (scores bounded by RMSNorm: |s|<14,
// softmax with fixed max 16 is mathematically identical). q pre-scaled by
// 0.125*log2e so the dot lands in log2 domain; p = ex2(dot - 16*log2e).
// grid = (B*H, S/128), block = 128, 1 thread = 1 query row.
// ---------------------------------------------------------------------------
__global__ __launch_bounds__(128) void attn_kernel()
{
    const int bh = blockIdx.x;
    const int qt = blockIdx.y;
    const float* __restrict__ Qp = g_q + (size_t)bh * SQ * CC;
    const float* __restrict__ Kp = g_k + (size_t)bh * SQ * CC;
    const float* __restrict__ Vp = g_v + (size_t)bh * SQ * CC;
    const int tid = threadIdx.x;
    const int qi  = qt * 128 + tid;

    __shared__ float Ks[64][64];
    __shared__ float Vs[64][64];

    const float QS = 0.18033688011112042f;   // 0.125 * log2(e)
    const float MB = 23.083120654223414f;    // 16 * log2(e)

    ull q2[32];
#pragma unroll
    for (int i = 0; i < 16; i++) {
        float4 t = *(const float4*)&Qp[(size_t)qi * CC + i * 4];
        q2[2 * i + 0] = pack2(t.x * QS, t.y * QS);
        q2[2 * i + 1] = pack2(t.z * QS, t.w * QS);
    }
    ull o2[32];
#pragma unroll
    for (int i = 0; i < 32; i++) o2[i] = 0ull;
    float l = 0.f;

#pragma unroll 1
    for (int j0 = 0; j0 < SQ; j0 += 64) {
        __syncthreads();
#pragma unroll
        for (int t = 0; t < 8; t++) {
            int lin = tid + t * 128;
            int row = lin >> 4;
            int c4  = (lin & 15) << 2;
            *(float4*)&Ks[row][c4] = *(const float4*)&Kp[(size_t)(j0 + row) * CC + c4];
            *(float4*)&Vs[row][c4] = *(const float4*)&Vp[(size_t)(j0 + row) * CC + c4];
        }
        __syncthreads();
#pragma unroll 2
        for (int j = 0; j < 64; j++) {
            const ulonglong2* Kr = (const ulonglong2*)&Ks[j][0];
            ull d0 = 0ull, d1 = 0ull, d2 = 0ull, d3 = 0ull;
#pragma unroll
            for (int t = 0; t < 8; t++) {
                ulonglong2 ka = Kr[2 * t], kb = Kr[2 * t + 1];
                ffma2(d0, q2[4 * t + 0], ka.x);
                ffma2(d1, q2[4 * t + 1], ka.y);
                ffma2(d2, q2[4 * t + 2], kb.x);
                ffma2(d3, q2[4 * t + 3], kb.y);
            }
            float2 s2 = unpack2(fadd2(fadd2(d0, d1), fadd2(d2, d3)));
            float p = ex2f(s2.x + s2.y - MB);
            l += p;
            ull p2 = pack2(p, p);
            const ulonglong2* Vr = (const ulonglong2*)&Vs[j][0];
#pragma unroll
            for (int t = 0; t < 8; t++) {
                ulonglong2 va = Vr[2 * t], vb = Vr[2 * t + 1];
                ffma2(o2[4 * t + 0], p2, va.x);
                ffma2(o2[4 * t + 1], p2, va.y);
                ffma2(o2[4 * t + 2], p2, vb.x);
                ffma2(o2[4 * t + 3], p2, vb.y);
            }
        }
    }

    float inv = 1.0f / l;
    int b = bh / HH, h = bh % HH;
    float* __restrict__ op = g_ao + ((size_t)qi * BB + b) * HC + h * CC;
#pragma unroll
    for (int t = 0; t < 16; t++) {
        float2 a = unpack2(o2[2 * t + 0]);
        float2 c = unpack2(o2[2 * t + 1]);
        *(float4*)&op[t * 4] = make_float4(a.x * inv, a.y * inv, c.x * inv, c.y * inv);
    }
}

// ---------------------------------------------------------------------------
// Kernel 3: output projection  g_ao(4096x1024) @ Wout(1024x1024) -> out
// grid = (DD/64, NROW/128)
// ---------------------------------------------------------------------------
__global__ __launch_bounds__(256) void outproj_kernel(
    const float* __restrict__ Wout, float* __restrict__ out)
{
    __shared__ MainSmem sm;

    const int n0 = blockIdx.x * 64;
    const int r0 = blockIdx.y * 128;

    const int tid = threadIdx.x;
    const int tx = tid & 15, ty = tid >> 4;

    ull acc[8][2];
#pragma unroll
    for (int i = 0; i < 8; i++) { acc[i][0] = 0ull; acc[i][1] = 0ull; }

    for (int k0 = 0; k0 < HC; k0 += 32) {
#pragma unroll
        for (int q = 0; q < 4; q++) {
            int lin = tid + q * 256;
            int mm  = lin >> 3;
            int kk  = (lin & 7) << 2;
            float4 a4 = *(const float4*)&g_ao[(size_t)(r0 + mm) * HC + k0 + kk];
            *(float2*)&sm.As2[kk + 0][2 * mm] = make_float2(a4.x, a4.x);
            *(float2*)&sm.As2[kk + 1][2 * mm] = make_float2(a4.y, a4.y);
            *(float2*)&sm.As2[kk + 2][2 * mm] = make_float2(a4.z, a4.z);
            *(float2*)&sm.As2[kk + 3][2 * mm] = make_float2(a4.w, a4.w);
        }
#pragma unroll
        for (int q = 0; q < 2; q++) {
            int lin = tid + q * 256;
            int kb = lin >> 4;
            int n4 = (lin & 15) << 2;
            *(float4*)&sm.Bs[kb][n4] = *(const float4*)&Wout[(size_t)(k0 + kb) * DD + n0 + n4];
        }
        __syncthreads();
#pragma unroll
        for (int kk = 0; kk < 32; kk++) {
            const ulonglong2* Ar = (const ulonglong2*)&sm.As2[kk][16 * ty];
            ulonglong2 a01 = Ar[0], a23 = Ar[1], a45 = Ar[2], a67 = Ar[3];
            ulonglong2 b2 = *(const ulonglong2*)&sm.Bs[kk][tx * 4];
            ffma2(acc[0][0], a01.x, b2.x); ffma2(acc[0][1], a01.x, b2.y);
            ffma2(acc[1][0], a01.y, b2.x); ffma2(acc[1][1], a01.y, b2.y);
            ffma2(acc[2][0], a23.x, b2.x); ffma2(acc[2][1], a23.x, b2.y);
            ffma2(acc[3][0], a23.y, b2.x); ffma2(acc[3][1], a23.y, b2.y);
            ffma2(acc[4][0], a45.x, b2.x); ffma2(acc[4][1], a45.x, b2.y);
            ffma2(acc[5][0], a45.y, b2.x); ffma2(acc[5][1], a45.y, b2.y);
            ffma2(acc[6][0], a67.x, b2.x); ffma2(acc[6][1], a67.x, b2.y);
            ffma2(acc[7][0], a67.y, b2.x); ffma2(acc[7][1], a67.y, b2.y);
        }
        __syncthreads();
    }

#pragma unroll
    for (int i = 0; i < 8; i++) {
        float2 v0 = unpack2(acc[i][0]);
        float2 v1 = unpack2(acc[i][1]);
        *(float4*)&out[(size_t)(r0 + ty * 8 + i) * DD + n0 + tx * 4] =
            make_float4(v0.x, v0.y, v1.x, v1.y);
    }
}

// ---------------------------------------------------------------------------
extern "C" void kernel_launch(void* const* d_in, const int* in_sizes, int n_in,
                              void* d_out, int out_size)
{
    (void)in_sizes; (void)n_in; (void)out_size;
    const float* x    = (const float*)d_in[0];
    const float* rope = (const float*)d_in[1];
    const float* Wq   = (const float*)d_in[2];
    const float* Wk   = (const float*)d_in[3];
    const float* Wv   = (const float*)d_in[4];
    const float* qw   = (const float*)d_in[5];
    const float* kw   = (const float*)d_in[6];
    const float* Wout = (const float*)d_in[7];
    float* out = (float*)d_out;

    dim3 g1(HH, NROW / 128, 3);
    qkv_kernel<<<g1, 256>>>(x, rope, Wq, Wk, Wv, qw, kw);

    dim3 g2(BB * HH, SQ / 128);
    attn_kernel<<<g2, 128>>>();

    dim3 g3(DD / 64, NROW / 128);
    outproj_kernel<<<g3, 256>>>(Wout, out);
}